// round 11
// baseline (speedup 1.0000x reference)
#include <cuda_runtime.h>
#include <cuda_bf16.h>
#include <cstdint>

#define IMG_H 480
#define IMG_W 640
#define IMG_HW (IMG_H * IMG_W)
#define OCH 64
#define KK 25
#define TKX 128          // CTA tile width (px)
#define TKY 2            // CTA tile rows
#define SW 132           // halo row width
#define SH 6             // halo rows
#define THREADS 128
#define PXC 256          // pixels per CTA
#define PXS2 260         // u64 stride per kp row  (== 4 mod 16 -> conflict-free LDS.64)
#define THRESH 1e-4f

// fragment-ordered split weights, built once by prep kernel:
// index = lane*64 + term*32 + mt*8 + s*4 + r   (term 0=Wh, 1=Wl)
__device__ uint32_t g_wfrag[2048];

__device__ __forceinline__ uint32_t bf16x2_of(float lo, float hi) {
    uint32_t r;
    asm("cvt.rn.bf16x2.f32 %0, %1, %2;" : "=r"(r) : "f"(hi), "f"(lo));  // first src = high half
    return r;
}
__device__ __forceinline__ void mma16816(float* d, const uint32_t* a, const uint32_t* b) {
    asm volatile(
        "mma.sync.aligned.m16n8k16.row.col.f32.bf16.bf16.f32 "
        "{%0,%1,%2,%3}, {%4,%5,%6,%7}, {%8,%9}, {%0,%1,%2,%3};"
        : "+f"(d[0]), "+f"(d[1]), "+f"(d[2]), "+f"(d[3])
        : "r"(a[0]), "r"(a[1]), "r"(a[2]), "r"(a[3]), "r"(b[0]), "r"(b[1]));
}

__global__ void prep_wfrag(const float* __restrict__ wt) {
    int i = blockIdx.x * blockDim.x + threadIdx.x;   // 0..2047
    if (i >= 2048) return;
    int r    = i & 3;
    int s    = (i >> 2) & 1;
    int mt   = (i >> 3) & 3;
    int term = (i >> 5) & 1;
    int lane = i >> 6;
    int g = lane >> 2, tig = lane & 3;
    int ch = mt * 16 + g + ((r & 1) ? 8 : 0);
    int kp = 8 * s + tig + ((r >> 1) ? 4 : 0);
    int k0 = 2 * kp, k1 = k0 + 1;
    float w0 = (k0 < KK) ? wt[ch * KK + k0] : 0.f;
    float w1 = (k1 < KK) ? wt[ch * KK + k1] : 0.f;
    uint32_t h = bf16x2_of(w0, w1);
    uint32_t v = h;
    if (term) {
        float h0 = __uint_as_float(h << 16);
        float h1 = __uint_as_float(h & 0xffff0000u);
        v = bf16x2_of(w0 - h0, w1 - h1);
    }
    g_wfrag[i] = v;
}

__global__ __launch_bounds__(THREADS, 4)
void normdepthconv_mma_kernel(const float* __restrict__ x,
                              float* __restrict__ out) {
    __shared__ float tile[SH * SW];                              // 3168 B halo
    __shared__ __align__(16) unsigned long long tpair[16 * PXS2]; // 33280 B {th,tl} per (kp,px)

    const int b   = blockIdx.z;
    const int X0  = blockIdx.x * TKX;
    const int Y0  = blockIdx.y * TKY;
    const int tid = threadIdx.x;
    const int lane = tid & 31;
    const int warp = tid >> 5;
    const int g    = lane >> 2;     // fragment row sel
    const int tig  = lane & 3;      // fragment col sel

    // ---- halo tile (zero-padded) ----
    const float* xb = x + (size_t)b * IMG_HW;
    for (int i = tid; i < SH * SW; i += THREADS) {
        int r = i / SW, c = i - r * SW;
        int gy = Y0 - 2 + r, gx = X0 - 2 + c;
        float v = 0.f;
        if (gy >= 0 && gy < IMG_H && gx >= 0 && gx < IMG_W) v = xb[gy * IMG_W + gx];
        tile[i] = v;
    }
    __syncthreads();

    // ---- t generation: 2 ADJACENT px/thread, float2 halo loads ----
    {
        const int p  = 2 * tid;          // even pixel index 0..254
        const int ty = p >> 7;
        const int xx = p & 127;
        float t0[KK + 1], t1[KK + 1];
        t0[KK] = 0.f; t1[KK] = 0.f;
        float S0 = 0.f, S1 = 0.f, Nv0 = 0.f, Nv1 = 0.f;
#pragma unroll
        for (int dy = 0; dy < 5; ++dy) {
            const float2* row = reinterpret_cast<const float2*>(&tile[(ty + dy) * SW + xx]);
            float2 a = row[0], c = row[1], e = row[2];
            float v[6] = {a.x, a.y, c.x, c.y, e.x, e.y};
#pragma unroll
            for (int kw = 0; kw < 5; ++kw) {
                const int k = dy * 5 + kw;
                t0[k] = v[kw];
                t1[k] = v[kw + 1];
                S0 += v[kw];     Nv0 += (v[kw]     > THRESH) ? 1.f : 0.f;
                S1 += v[kw + 1]; Nv1 += (v[kw + 1] > THRESH) ? 1.f : 0.f;
            }
        }
        const float ref0 = S0 / (Nv0 + 1e-6f);
        const float ref1 = S1 / (Nv1 + 1e-6f);
#pragma unroll
        for (int k = 0; k < KK; ++k) {
            t0[k] = (t0[k] > THRESH) ? (ref0 - t0[k]) : 0.f;
            t1[k] = (t1[k] > THRESH) ? (ref1 - t1[k]) : 0.f;
        }
#pragma unroll
        for (int j = 0; j < 16; ++j) {
            unsigned long long w0 = 0ull, w1 = 0ull;
            if (2 * j < KK) {
                uint32_t h0 = bf16x2_of(t0[2 * j], t0[2 * j + 1]);
                uint32_t h1 = bf16x2_of(t1[2 * j], t1[2 * j + 1]);
                float a0 = __uint_as_float(h0 << 16), b0 = __uint_as_float(h0 & 0xffff0000u);
                float a1 = __uint_as_float(h1 << 16), b1 = __uint_as_float(h1 & 0xffff0000u);
                uint32_t l0 = bf16x2_of(t0[2 * j] - a0, t0[2 * j + 1] - b0);
                uint32_t l1 = bf16x2_of(t1[2 * j] - a1, t1[2 * j + 1] - b1);
                w0 = (unsigned long long)h0 | ((unsigned long long)l0 << 32);
                w1 = (unsigned long long)h1 | ((unsigned long long)l1 << 32);
            }
            *reinterpret_cast<ulonglong2*>(&tpair[j * PXS2 + p]) = make_ulonglong2(w0, w1);
        }
    }
    __syncthreads();

    // ---- W fragments: LDG.128 of pre-formatted data (L2-resident), post-sync ----
    uint32_t Wf[2][4][2][4];
    {
        const uint4* wp = reinterpret_cast<const uint4*>(g_wfrag + lane * 64);
#pragma unroll
        for (int q = 0; q < 16; ++q) {          // q = term*8 + mt*2 + s
            uint4 u = wp[q];
            const int term = q >> 3, mt = (q >> 1) & 3, s = q & 1;
            Wf[term][mt][s][0] = u.x;
            Wf[term][mt][s][1] = u.y;
            Wf[term][mt][s][2] = u.z;
            Wf[term][mt][s][3] = u.w;
        }
    }

    // ---- GEMM: warp covers 64 px; D[64ch x 8px] tiles via HMMA ----
    float* outb = out + (size_t)b * OCH * IMG_HW;

#pragma unroll
    for (int nc = 0; nc < 8; ++nc) {
        const int n0  = warp * 64 + nc * 8;
        const int col = n0 + g;

        uint32_t bth[2][2], btl[2][2];
#pragma unroll
        for (int s = 0; s < 2; ++s) {
            unsigned long long v0 = tpair[(8 * s + tig)     * PXS2 + col];
            unsigned long long v1 = tpair[(8 * s + tig + 4) * PXS2 + col];
            bth[s][0] = (uint32_t)v0;  btl[s][0] = (uint32_t)(v0 >> 32);
            bth[s][1] = (uint32_t)v1;  btl[s][1] = (uint32_t)(v1 >> 32);
        }

        float acc[4][4];
#pragma unroll
        for (int mt = 0; mt < 4; ++mt)
#pragma unroll
            for (int r = 0; r < 4; ++r) acc[mt][r] = 0.f;

#pragma unroll
        for (int mt = 0; mt < 4; ++mt) {
#pragma unroll
            for (int s = 0; s < 2; ++s) mma16816(acc[mt], Wf[0][mt][s], bth[s]);
#pragma unroll
            for (int s = 0; s < 2; ++s) mma16816(acc[mt], Wf[0][mt][s], btl[s]);
#pragma unroll
            for (int s = 0; s < 2; ++s) mma16816(acc[mt], Wf[1][mt][s], bth[s]);
        }

        // ---- store: lane owns adjacent px pair per channel ----
        const int p0  = n0 + 2 * tig;
        const int row = p0 >> 7;
        const int xo  = p0 & 127;
        float* base = outb + (size_t)(Y0 + row) * IMG_W + (X0 + xo);
#pragma unroll
        for (int mt = 0; mt < 4; ++mt) {
            const int ch = mt * 16 + g;
            *reinterpret_cast<float2*>(base + (size_t)ch * IMG_HW) =
                make_float2(acc[mt][0], acc[mt][1]);
            *reinterpret_cast<float2*>(base + (size_t)(ch + 8) * IMG_HW) =
                make_float2(acc[mt][2], acc[mt][3]);
        }
    }
}

extern "C" void kernel_launch(void* const* d_in, const int* in_sizes, int n_in,
                              void* d_out, int out_size) {
    const float* x = (const float*)d_in[0];
    const float* w = (const float*)d_in[1];
    if (n_in >= 2 && in_sizes[0] == OCH * KK) {   // defensive input-order check
        x = (const float*)d_in[1];
        w = (const float*)d_in[0];
    }
    prep_wfrag<<<16, 128>>>(w);
    dim3 grid(IMG_W / TKX, IMG_H / TKY, 8);   // 5 x 240 x 8 = 9600 CTAs
    normdepthconv_mma_kernel<<<grid, THREADS>>>(x, (float*)d_out);
}

// round 12
// speedup vs baseline: 1.2421x; 1.2421x over previous
#include <cuda_runtime.h>
#include <cuda_bf16.h>
#include <cstdint>

#define IMG_H 480
#define IMG_W 640
#define IMG_HW (IMG_H * IMG_W)
#define OCH 64
#define KK 25
#define TKX 128          // CTA tile width (px)
#define TKY 2            // CTA tile rows -> 256 px per CTA
#define HW2 134          // halo tile cols (132 + 2 safety)
#define PW 140           // plane2 row stride (u32) -> fragment-load bank separation
#define THREADS 128
#define THRESH 1e-4f

// fragment-ordered split weights, K'=32 layout (kp j: dy=j/3, kw-pair 2*(j%3)):
// g_wfrag[((mt*32 + lane)*16) + term*8 + s*4 + r]
__device__ uint32_t g_wfrag[2048];

__device__ __forceinline__ uint32_t bf16x2_of(float lo, float hi) {
    uint32_t r;
    asm("cvt.rn.bf16x2.f32 %0, %1, %2;" : "=r"(r) : "f"(hi), "f"(lo));  // first src = high half
    return r;
}
__device__ __forceinline__ void mma16816(float* d, const uint32_t* a, const uint32_t* b) {
    asm volatile(
        "mma.sync.aligned.m16n8k16.row.col.f32.bf16.bf16.f32 "
        "{%0,%1,%2,%3}, {%4,%5,%6,%7}, {%8,%9}, {%0,%1,%2,%3};"
        : "+f"(d[0]), "+f"(d[1]), "+f"(d[2]), "+f"(d[3])
        : "r"(a[0]), "r"(a[1]), "r"(a[2]), "r"(a[3]), "r"(b[0]), "r"(b[1]));
}

__global__ void prep_wfrag(const float* __restrict__ wt) {
    int i = blockIdx.x * blockDim.x + threadIdx.x;   // 0..2047
    if (i >= 2048) return;
    int q    = i & 15;
    int lane = (i >> 4) & 31;
    int mt   = i >> 9;
    int term = q >> 3;
    int s    = (q >> 2) & 1;
    int r    = q & 3;
    int g = lane >> 2, tig = lane & 3;
    int ch = mt * 16 + g + ((r & 1) ? 8 : 0);
    int j  = 8 * s + tig + ((r >> 1) ? 4 : 0);       // kp row 0..15
    float w0 = 0.f, w1 = 0.f;
    if (j < 15) {
        int dy = j / 3, m = j - 3 * dy;
        int k0 = dy * 5 + 2 * m;
        w0 = wt[ch * KK + k0];
        if (2 * m + 1 < 5) w1 = wt[ch * KK + k0 + 1];
    }
    uint32_t h = bf16x2_of(w0, w1);
    uint32_t v = h;
    if (term) {
        float h0 = __uint_as_float(h << 16);
        float h1 = __uint_as_float(h & 0xffff0000u);
        v = bf16x2_of(w0 - h0, w1 - h1);
    }
    g_wfrag[i] = v;
}

__global__ __launch_bounds__(THREADS, 6)
void normdepthconv_plane_kernel(const float* __restrict__ x,
                                float* __restrict__ out) {
    __shared__ float    tile[6 * HW2];     // 3216 B raw halo (f32)
    __shared__ float    rowsx[6 * 128];    // 3072 B 5-tap row sums of x
    __shared__ float    rowsm[6 * 128];    // 3072 B 5-tap row sums of mask
    __shared__ float    refp[256];         // 1024 B per-output-px ref
    __shared__ uint32_t m2 [6 * PW];       // 3360 B mask plane, {v[h],v[h+1]} bf16x2
    __shared__ uint32_t yh2[6 * PW];       // y-high plane
    __shared__ uint32_t yl2[6 * PW];       // y-low  plane

    const int b   = blockIdx.z;
    const int X0  = blockIdx.x * TKX;
    const int Y0  = blockIdx.y * TKY;
    const int tid = threadIdx.x;
    const int lane = tid & 31;
    const int warp = tid >> 5;             // == mt (channel tile), warp-specialized
    const int g    = lane >> 2;
    const int tig  = lane & 3;

    // ---- weight fragments for this warp's mt: 4x LDG.128, early for MLP ----
    uint32_t Wh[2][4], Wl[2][4];
    {
        const uint4* wp = reinterpret_cast<const uint4*>(g_wfrag + (warp * 32 + lane) * 16);
        uint4 u0 = wp[0], u1 = wp[1], u2 = wp[2], u3 = wp[3];
        Wh[0][0] = u0.x; Wh[0][1] = u0.y; Wh[0][2] = u0.z; Wh[0][3] = u0.w;
        Wh[1][0] = u1.x; Wh[1][1] = u1.y; Wh[1][2] = u1.z; Wh[1][3] = u1.w;
        Wl[0][0] = u2.x; Wl[0][1] = u2.y; Wl[0][2] = u2.z; Wl[0][3] = u2.w;
        Wl[1][0] = u3.x; Wl[1][1] = u3.y; Wl[1][2] = u3.z; Wl[1][3] = u3.w;
    }

    // ---- halo tile load (zero-padded borders) ----
    const float* xb = x + (size_t)b * IMG_HW;
    for (int i = tid; i < 6 * HW2; i += THREADS) {
        int r = i / HW2, c = i - r * HW2;
        int gy = Y0 - 2 + r, gx = X0 - 2 + c;
        float v = 0.f;
        if (gy >= 0 && gy < IMG_H && gx >= 0 && gx < IMG_W) v = xb[gy * IMG_W + gx];
        tile[i] = v;
    }
    __syncthreads();

    // ---- 5-tap row sums (x and mask) + bf16 plane generation ----
    for (int q = tid; q < 6 * 128; q += THREADS) {
        int r = q >> 7, i = q & 127;
        const float* tr = &tile[r * HW2 + i];
        float sx = 0.f, sm = 0.f;
#pragma unroll
        for (int kw = 0; kw < 5; ++kw) {
            float v = tr[kw];
            sx += v;
            sm += (v > THRESH) ? 1.f : 0.f;
        }
        rowsx[q] = sx;
        rowsm[q] = sm;
    }
    for (int q = tid; q < 6 * 132; q += THREADS) {
        int r = q / 132, h = q - r * 132;
        float x0 = tile[r * HW2 + h], x1 = tile[r * HW2 + h + 1];
        float mk0 = (x0 > THRESH) ? 1.f : 0.f;
        float mk1 = (x1 > THRESH) ? 1.f : 0.f;
        float y0 = x0 * mk0, y1 = x1 * mk1;
        uint32_t hh = bf16x2_of(y0, y1);
        float e0 = y0 - __uint_as_float(hh << 16);
        float e1 = y1 - __uint_as_float(hh & 0xffff0000u);
        m2 [r * PW + h] = bf16x2_of(mk0, mk1);
        yh2[r * PW + h] = hh;
        yl2[r * PW + h] = bf16x2_of(e0, e1);
    }
    __syncthreads();

    // ---- 5-tap column sums -> ref per output pixel ----
    for (int q = tid; q < 256; q += THREADS) {
        int ry = q >> 7, i = q & 127;
        float Sx = 0.f, Sm = 0.f;
#pragma unroll
        for (int dy = 0; dy < 5; ++dy) {
            Sx += rowsx[(ry + dy) * 128 + i];
            Sm += rowsm[(ry + dy) * 128 + i];
        }
        refp[q] = Sx / (Sm + 1e-6f);
    }
    __syncthreads();

    // ---- fragment gather offsets (loop-invariant): j = 8s + tig (+4) ----
    int ofs[2][2];
#pragma unroll
    for (int s = 0; s < 2; ++s) {
#pragma unroll
        for (int ri = 0; ri < 2; ++ri) {
            int j = 8 * s + tig + 4 * ri;
            int dy = 0, m = 0;
            if (j < 15) { dy = j / 3; m = j - 3 * dy; }
            ofs[s][ri] = dy * PW + 2 * m;
        }
    }

    // ---- GEMM: this warp does ALL 256 px for its 16 channels ----
    const int ch0 = warp * 16 + g;
    float* outb = out + (size_t)b * OCH * IMG_HW;
    float* op0  = outb + (size_t)ch0 * IMG_HW;       // row ch0
    float* op1  = op0 + (size_t)8 * IMG_HW;          // row ch0+8

#pragma unroll 4
    for (int nc = 0; nc < 32; ++nc) {
        const int px = nc * 8 + g;                   // b-frag column pixel
        const int base = (px >> 7) * PW + (px & 127);

        uint32_t bm[2][2], by[2][2], bl[2][2];
#pragma unroll
        for (int s = 0; s < 2; ++s) {
#pragma unroll
            for (int ri = 0; ri < 2; ++ri) {
                int a = base + ofs[s][ri];
                bm[s][ri] = m2 [a];
                by[s][ri] = yh2[a];
                bl[s][ri] = yl2[a];
            }
        }

        float accA[4] = {0.f, 0.f, 0.f, 0.f};
        float accB[4] = {0.f, 0.f, 0.f, 0.f};
#pragma unroll
        for (int s = 0; s < 2; ++s) {
            mma16816(accA, Wh[s], bm[s]);
            mma16816(accB, Wh[s], by[s]);
            mma16816(accA, Wl[s], bm[s]);
            mma16816(accB, Wl[s], by[s]);
            mma16816(accB, Wh[s], bl[s]);
        }

        // ---- epilogue: out = ref*A - B ; lane owns adjacent px pair ----
        const int p0  = nc * 8 + 2 * tig;
        const float2 rv = *reinterpret_cast<const float2*>(&refp[p0]);
        const int row = p0 >> 7;
        const int xo  = p0 & 127;
        const size_t off = (size_t)(Y0 + row) * IMG_W + (X0 + xo);
        *reinterpret_cast<float2*>(op0 + off) =
            make_float2(fmaf(rv.x, accA[0], -accB[0]), fmaf(rv.y, accA[1], -accB[1]));
        *reinterpret_cast<float2*>(op1 + off) =
            make_float2(fmaf(rv.x, accA[2], -accB[2]), fmaf(rv.y, accA[3], -accB[3]));
    }
}

extern "C" void kernel_launch(void* const* d_in, const int* in_sizes, int n_in,
                              void* d_out, int out_size) {
    const float* x = (const float*)d_in[0];
    const float* w = (const float*)d_in[1];
    if (n_in >= 2 && in_sizes[0] == OCH * KK) {   // defensive input-order check
        x = (const float*)d_in[1];
        w = (const float*)d_in[0];
    }
    prep_wfrag<<<16, 128>>>(w);
    dim3 grid(IMG_W / TKX, IMG_H / TKY, 8);   // 5 x 240 x 8 = 9600 CTAs
    normdepthconv_plane_kernel<<<grid, THREADS>>>(x, (float*)d_out);
}

// round 13
// speedup vs baseline: 1.3455x; 1.0833x over previous
#include <cuda_runtime.h>
#include <cuda_bf16.h>
#include <cstdint>

#define IMG_H 480
#define IMG_W 640
#define IMG_HW (IMG_H * IMG_W)
#define OCH 64
#define KK 25
#define TKX 128          // CTA tile width (px)
#define TKY 2            // CTA tile rows -> 256 px per CTA
#define HW2 134          // halo tile cols (132 + 2 safety)
#define PW 140           // plane row stride (u32) -> fragment-load bank separation
#define THREADS 128
#define THRESH 1e-4f

// fragment-ordered split weights, K'=32 layout (kp j: dy=j/3, kw-pair 2*(j%3)):
// g_wfrag[((mt*32 + lane)*16) + term*8 + s*4 + r]
__device__ uint32_t g_wfrag[2048];

__device__ __forceinline__ uint32_t bf16x2_of(float lo, float hi) {
    uint32_t r;
    asm("cvt.rn.bf16x2.f32 %0, %1, %2;" : "=r"(r) : "f"(hi), "f"(lo));  // first src = high half
    return r;
}
__device__ __forceinline__ void mma16816(float* d, const uint32_t* a, const uint32_t* b) {
    asm volatile(
        "mma.sync.aligned.m16n8k16.row.col.f32.bf16.bf16.f32 "
        "{%0,%1,%2,%3}, {%4,%5,%6,%7}, {%8,%9}, {%0,%1,%2,%3};"
        : "+f"(d[0]), "+f"(d[1]), "+f"(d[2]), "+f"(d[3])
        : "r"(a[0]), "r"(a[1]), "r"(a[2]), "r"(a[3]), "r"(b[0]), "r"(b[1]));
}

__global__ void prep_wfrag(const float* __restrict__ wt) {
    int i = blockIdx.x * blockDim.x + threadIdx.x;   // 0..2047
    if (i >= 2048) return;
    int q    = i & 15;
    int lane = (i >> 4) & 31;
    int mt   = i >> 9;
    int term = q >> 3;
    int s    = (q >> 2) & 1;
    int r    = q & 3;
    int g = lane >> 2, tig = lane & 3;
    int ch = mt * 16 + g + ((r & 1) ? 8 : 0);
    int j  = 8 * s + tig + ((r >> 1) ? 4 : 0);       // kp row 0..15
    float w0 = 0.f, w1 = 0.f;
    if (j < 15) {
        int dy = j / 3, m = j - 3 * dy;
        int k0 = dy * 5 + 2 * m;
        w0 = wt[ch * KK + k0];
        if (2 * m + 1 < 5) w1 = wt[ch * KK + k0 + 1];
    }
    uint32_t h = bf16x2_of(w0, w1);
    uint32_t v = h;
    if (term) {
        float h0 = __uint_as_float(h << 16);
        float h1 = __uint_as_float(h & 0xffff0000u);
        v = bf16x2_of(w0 - h0, w1 - h1);
    }
    g_wfrag[i] = v;
}

__global__ __launch_bounds__(THREADS, 5)
void normdepthconv_plane_kernel(const float* __restrict__ x,
                                float* __restrict__ out) {
    __shared__ float    tile[6 * HW2];     // 3216 B raw halo (f32)
    __shared__ float    rowsx[6 * 128];    // 3072 B 5-tap row sums of x
    __shared__ float    rowsm[6 * 128];    // 3072 B 5-tap row sums of mask
    __shared__ float    refp[256];         // 1024 B per-output-px ref
    __shared__ uint32_t m2 [6 * PW];       // 3360 B mask plane, {v[h],v[h+1]} bf16x2
    __shared__ uint32_t yh2[6 * PW];       // y-high plane
    __shared__ uint32_t yl2[6 * PW];       // y-low  plane

    const int b   = blockIdx.z;
    const int X0  = blockIdx.x * TKX;
    const int Y0  = blockIdx.y * TKY;
    const int tid = threadIdx.x;
    const int lane = tid & 31;
    const int warp = tid >> 5;
    const int g    = lane >> 2;
    const int tig  = lane & 3;

    // warp partition: row = which 128-px image row, mt0 = first of two ch tiles
    const int wrow = warp >> 1;            // 0 or 1
    const int mt0  = (warp & 1) * 2;       // {0,1} or {2,3}

    // ---- weight fragments for mt0, mt0+1: 8x LDG.128, early for MLP ----
    uint32_t Wh[2][2][4], Wl[2][2][4];
#pragma unroll
    for (int m = 0; m < 2; ++m) {
        const uint4* wp =
            reinterpret_cast<const uint4*>(g_wfrag + ((mt0 + m) * 32 + lane) * 16);
        uint4 u0 = wp[0], u1 = wp[1], u2 = wp[2], u3 = wp[3];
        Wh[m][0][0] = u0.x; Wh[m][0][1] = u0.y; Wh[m][0][2] = u0.z; Wh[m][0][3] = u0.w;
        Wh[m][1][0] = u1.x; Wh[m][1][1] = u1.y; Wh[m][1][2] = u1.z; Wh[m][1][3] = u1.w;
        Wl[m][0][0] = u2.x; Wl[m][0][1] = u2.y; Wl[m][0][2] = u2.z; Wl[m][0][3] = u2.w;
        Wl[m][1][0] = u3.x; Wl[m][1][1] = u3.y; Wl[m][1][2] = u3.z; Wl[m][1][3] = u3.w;
    }

    // ---- halo tile load (zero-padded borders) ----
    const float* xb = x + (size_t)b * IMG_HW;
    for (int i = tid; i < 6 * HW2; i += THREADS) {
        int r = i / HW2, c = i - r * HW2;
        int gy = Y0 - 2 + r, gx = X0 - 2 + c;
        float v = 0.f;
        if (gy >= 0 && gy < IMG_H && gx >= 0 && gx < IMG_W) v = xb[gy * IMG_W + gx];
        tile[i] = v;
    }
    __syncthreads();

    // ---- 5-tap row sums (x and mask) + bf16 plane generation ----
    for (int q = tid; q < 6 * 128; q += THREADS) {
        int r = q >> 7, i = q & 127;
        const float* tr = &tile[r * HW2 + i];
        float sx = 0.f, sm = 0.f;
#pragma unroll
        for (int kw = 0; kw < 5; ++kw) {
            float v = tr[kw];
            sx += v;
            sm += (v > THRESH) ? 1.f : 0.f;
        }
        rowsx[q] = sx;
        rowsm[q] = sm;
    }
    for (int q = tid; q < 6 * 132; q += THREADS) {
        int r = q / 132, h = q - r * 132;
        float x0 = tile[r * HW2 + h], x1 = tile[r * HW2 + h + 1];
        float mk0 = (x0 > THRESH) ? 1.f : 0.f;
        float mk1 = (x1 > THRESH) ? 1.f : 0.f;
        float y0 = x0 * mk0, y1 = x1 * mk1;
        uint32_t hh = bf16x2_of(y0, y1);
        float e0 = y0 - __uint_as_float(hh << 16);
        float e1 = y1 - __uint_as_float(hh & 0xffff0000u);
        m2 [r * PW + h] = bf16x2_of(mk0, mk1);
        yh2[r * PW + h] = hh;
        yl2[r * PW + h] = bf16x2_of(e0, e1);
    }
    __syncthreads();

    // ---- 5-tap column sums -> ref per output pixel ----
    for (int q = tid; q < 256; q += THREADS) {
        int ry = q >> 7, i = q & 127;
        float Sx = 0.f, Sm = 0.f;
#pragma unroll
        for (int dy = 0; dy < 5; ++dy) {
            Sx += rowsx[(ry + dy) * 128 + i];
            Sm += rowsm[(ry + dy) * 128 + i];
        }
        refp[q] = Sx / (Sm + 1e-6f);
    }
    __syncthreads();

    // ---- fragment gather offsets (loop-invariant): j = 8s + tig (+4) ----
    int ofs[2][2];
#pragma unroll
    for (int s = 0; s < 2; ++s) {
#pragma unroll
        for (int ri = 0; ri < 2; ++ri) {
            int j = 8 * s + tig + 4 * ri;
            int dy = 0, m = 0;
            if (j < 15) { dy = j / 3; m = j - 3 * dy; }
            ofs[s][ri] = dy * PW + 2 * m;
        }
    }

    // ---- GEMM: warp does 128 px (its row) x 32 ch (mt0, mt0+1) ----
    float* outb = out + (size_t)b * OCH * IMG_HW;
    const size_t rowoff = (size_t)(Y0 + wrow) * IMG_W + X0;
    float* op[2][2];
#pragma unroll
    for (int m = 0; m < 2; ++m) {
        const int ch0 = (mt0 + m) * 16 + g;
        op[m][0] = outb + (size_t)ch0 * IMG_HW + rowoff;
        op[m][1] = op[m][0] + (size_t)8 * IMG_HW;
    }
    const int pbase = wrow * PW;           // warp-constant plane row base

#pragma unroll 4
    for (int nc = 0; nc < 16; ++nc) {
        const int xg = nc * 8 + g;                 // b-frag column (within row)
        const int base = pbase + xg;

        uint32_t bm[2][2], by[2][2], bl[2][2];
#pragma unroll
        for (int s = 0; s < 2; ++s) {
#pragma unroll
            for (int ri = 0; ri < 2; ++ri) {
                int a = base + ofs[s][ri];
                bm[s][ri] = m2 [a];
                by[s][ri] = yh2[a];
                bl[s][ri] = yl2[a];
            }
        }

        float accA[2][4] = {{0.f, 0.f, 0.f, 0.f}, {0.f, 0.f, 0.f, 0.f}};
        float accB[2][4] = {{0.f, 0.f, 0.f, 0.f}, {0.f, 0.f, 0.f, 0.f}};
#pragma unroll
        for (int s = 0; s < 2; ++s) {
#pragma unroll
            for (int m = 0; m < 2; ++m) {
                mma16816(accA[m], Wh[m][s], bm[s]);
                mma16816(accB[m], Wh[m][s], by[s]);
                mma16816(accA[m], Wl[m][s], bm[s]);
                mma16816(accB[m], Wl[m][s], by[s]);
                mma16816(accB[m], Wh[m][s], bl[s]);
            }
        }

        // ---- epilogue: out = ref*A - B ; lane owns adjacent px pair ----
        const int xo = nc * 8 + 2 * tig;
        const float2 rv = *reinterpret_cast<const float2*>(&refp[wrow * 128 + xo]);
#pragma unroll
        for (int m = 0; m < 2; ++m) {
            *reinterpret_cast<float2*>(op[m][0] + xo) =
                make_float2(fmaf(rv.x, accA[m][0], -accB[m][0]),
                            fmaf(rv.y, accA[m][1], -accB[m][1]));
            *reinterpret_cast<float2*>(op[m][1] + xo) =
                make_float2(fmaf(rv.x, accA[m][2], -accB[m][2]),
                            fmaf(rv.y, accA[m][3], -accB[m][3]));
        }
    }
}

extern "C" void kernel_launch(void* const* d_in, const int* in_sizes, int n_in,
                              void* d_out, int out_size) {
    const float* x = (const float*)d_in[0];
    const float* w = (const float*)d_in[1];
    if (n_in >= 2 && in_sizes[0] == OCH * KK) {   // defensive input-order check
        x = (const float*)d_in[1];
        w = (const float*)d_in[0];
    }
    prep_wfrag<<<16, 128>>>(w);
    dim3 grid(IMG_W / TKX, IMG_H / TKY, 8);   // 5 x 240 x 8 = 9600 CTAs
    normdepthconv_plane_kernel<<<grid, THREADS>>>(x, (float*)d_out);
}

// round 14
// speedup vs baseline: 1.3621x; 1.0123x over previous
#include <cuda_runtime.h>
#include <cuda_bf16.h>
#include <cstdint>

#define IMG_H 480
#define IMG_W 640
#define IMG_HW (IMG_H * IMG_W)
#define OCH 64
#define KK 25
#define TKX 128          // CTA tile width (px)
#define TKY 2            // CTA tile rows -> 256 px per CTA
#define HW2 134          // halo tile cols
#define PW 140           // plane row stride (u32)
#define SP 36            // stage row stride (u32), 16B-aligned rows
#define THREADS 128
#define THRESH 1e-4f

// fragment-ordered split weights, K'=32 layout (kp j: dy=j/3, kw-pair 2*(j%3)):
// g_wfrag[((mt*32 + lane)*16) + term*8 + s*4 + r]
__device__ uint32_t g_wfrag[2048];

__device__ __forceinline__ uint32_t bf16x2_of(float lo, float hi) {
    uint32_t r;
    asm("cvt.rn.bf16x2.f32 %0, %1, %2;" : "=r"(r) : "f"(hi), "f"(lo));  // first src = high half
    return r;
}
__device__ __forceinline__ void mma16816(float* d, const uint32_t* a, const uint32_t* b) {
    asm volatile(
        "mma.sync.aligned.m16n8k16.row.col.f32.bf16.bf16.f32 "
        "{%0,%1,%2,%3}, {%4,%5,%6,%7}, {%8,%9}, {%0,%1,%2,%3};"
        : "+f"(d[0]), "+f"(d[1]), "+f"(d[2]), "+f"(d[3])
        : "r"(a[0]), "r"(a[1]), "r"(a[2]), "r"(a[3]), "r"(b[0]), "r"(b[1]));
}

__global__ void prep_wfrag(const float* __restrict__ wt) {
    int i = blockIdx.x * blockDim.x + threadIdx.x;   // 0..2047
    if (i >= 2048) return;
    int q    = i & 15;
    int lane = (i >> 4) & 31;
    int mt   = i >> 9;
    int term = q >> 3;
    int s    = (q >> 2) & 1;
    int r    = q & 3;
    int g = lane >> 2, tig = lane & 3;
    int ch = mt * 16 + g + ((r & 1) ? 8 : 0);
    int j  = 8 * s + tig + ((r >> 1) ? 4 : 0);       // kp row 0..15
    float w0 = 0.f, w1 = 0.f;
    if (j < 15) {
        int dy = j / 3, m = j - 3 * dy;
        int k0 = dy * 5 + 2 * m;
        w0 = wt[ch * KK + k0];
        if (2 * m + 1 < 5) w1 = wt[ch * KK + k0 + 1];
    }
    uint32_t h = bf16x2_of(w0, w1);
    uint32_t v = h;
    if (term) {
        float h0 = __uint_as_float(h << 16);
        float h1 = __uint_as_float(h & 0xffff0000u);
        v = bf16x2_of(w0 - h0, w1 - h1);
    }
    g_wfrag[i] = v;
}

__global__ __launch_bounds__(THREADS, 5)
void normdepthconv_plane_kernel(const float* __restrict__ x,
                                float* __restrict__ out) {
    __shared__ float    tile[6 * HW2];     // raw halo (f32)
    __shared__ float    rowsx[6 * 128];    // 5-tap row sums of x
    __shared__ float    rowsm[6 * 128];    // 5-tap row sums of mask
    __shared__ float    refp[256];         // per-output-px ref
    __shared__ uint32_t m2 [6 * PW];       // mask plane bf16x2
    __shared__ uint32_t yh2[6 * PW];       // y-high plane
    __shared__ uint32_t yl2[6 * PW];       // y-low  plane
    __shared__ __align__(16) float stage[4 * 32 * SP];  // 18432 B, per-warp 32ch x 32px

    const int b   = blockIdx.z;
    const int X0  = blockIdx.x * TKX;
    const int Y0  = blockIdx.y * TKY;
    const int tid = threadIdx.x;
    const int lane = tid & 31;
    const int warp = tid >> 5;
    const int g    = lane >> 2;
    const int tig  = lane & 3;

    // warp partition: wrow = 128-px image row, mt0 = first of two ch tiles
    const int wrow = warp >> 1;            // 0 or 1
    const int mt0  = (warp & 1) * 2;       // {0,1} or {2,3}

    // ---- weight fragments for mt0, mt0+1: 8x LDG.128, early for MLP ----
    uint32_t Wh[2][2][4], Wl[2][2][4];
#pragma unroll
    for (int m = 0; m < 2; ++m) {
        const uint4* wp =
            reinterpret_cast<const uint4*>(g_wfrag + ((mt0 + m) * 32 + lane) * 16);
        uint4 u0 = wp[0], u1 = wp[1], u2 = wp[2], u3 = wp[3];
        Wh[m][0][0] = u0.x; Wh[m][0][1] = u0.y; Wh[m][0][2] = u0.z; Wh[m][0][3] = u0.w;
        Wh[m][1][0] = u1.x; Wh[m][1][1] = u1.y; Wh[m][1][2] = u1.z; Wh[m][1][3] = u1.w;
        Wl[m][0][0] = u2.x; Wl[m][0][1] = u2.y; Wl[m][0][2] = u2.z; Wl[m][0][3] = u2.w;
        Wl[m][1][0] = u3.x; Wl[m][1][1] = u3.y; Wl[m][1][2] = u3.z; Wl[m][1][3] = u3.w;
    }

    // ---- halo tile load (zero-padded borders) ----
    const float* xb = x + (size_t)b * IMG_HW;
    for (int i = tid; i < 6 * HW2; i += THREADS) {
        int r = i / HW2, c = i - r * HW2;
        int gy = Y0 - 2 + r, gx = X0 - 2 + c;
        float v = 0.f;
        if (gy >= 0 && gy < IMG_H && gx >= 0 && gx < IMG_W) v = xb[gy * IMG_W + gx];
        tile[i] = v;
    }
    __syncthreads();

    // ---- 5-tap row sums (x and mask) + bf16 plane generation ----
    for (int q = tid; q < 6 * 128; q += THREADS) {
        int r = q >> 7, i = q & 127;
        const float* tr = &tile[r * HW2 + i];
        float sx = 0.f, sm = 0.f;
#pragma unroll
        for (int kw = 0; kw < 5; ++kw) {
            float v = tr[kw];
            sx += v;
            sm += (v > THRESH) ? 1.f : 0.f;
        }
        rowsx[q] = sx;
        rowsm[q] = sm;
    }
    for (int q = tid; q < 6 * 132; q += THREADS) {
        int r = q / 132, h = q - r * 132;
        float x0 = tile[r * HW2 + h], x1 = tile[r * HW2 + h + 1];
        float mk0 = (x0 > THRESH) ? 1.f : 0.f;
        float mk1 = (x1 > THRESH) ? 1.f : 0.f;
        float y0 = x0 * mk0, y1 = x1 * mk1;
        uint32_t hh = bf16x2_of(y0, y1);
        float e0 = y0 - __uint_as_float(hh << 16);
        float e1 = y1 - __uint_as_float(hh & 0xffff0000u);
        m2 [r * PW + h] = bf16x2_of(mk0, mk1);
        yh2[r * PW + h] = hh;
        yl2[r * PW + h] = bf16x2_of(e0, e1);
    }
    __syncthreads();

    // ---- 5-tap column sums -> ref per output pixel ----
    for (int q = tid; q < 256; q += THREADS) {
        int ry = q >> 7, i = q & 127;
        float Sx = 0.f, Sm = 0.f;
#pragma unroll
        for (int dy = 0; dy < 5; ++dy) {
            Sx += rowsx[(ry + dy) * 128 + i];
            Sm += rowsm[(ry + dy) * 128 + i];
        }
        refp[q] = Sx / (Sm + 1e-6f);
    }
    __syncthreads();

    // ---- fragment gather offsets (loop-invariant): j = 8s + tig (+4) ----
    int ofs[2][2];
#pragma unroll
    for (int s = 0; s < 2; ++s) {
#pragma unroll
        for (int ri = 0; ri < 2; ++ri) {
            int j = 8 * s + tig + 4 * ri;
            int dy = 0, m = 0;
            if (j < 15) { dy = j / 3; m = j - 3 * dy; }
            ofs[s][ri] = dy * PW + 2 * m;
        }
    }

    // ---- GEMM + staged epilogue: warp = 128 px x 32 ch (mt0, mt0+1) ----
    float* wb = stage + warp * (32 * SP);
    float* obase = out + (size_t)b * OCH * IMG_HW + (size_t)(mt0 * 16) * IMG_HW +
                   (size_t)(Y0 + wrow) * IMG_W + X0;
    const int pbase = wrow * PW;           // warp-constant plane row base
    const int rr  = lane >> 3;             // read-phase row-in-quad
    const int pxl = 4 * (lane & 7);        // read-phase px offset

#pragma unroll 1
    for (int gi = 0; gi < 4; ++gi) {       // 4 groups of 32 px
#pragma unroll
        for (int ncl = 0; ncl < 4; ++ncl) {
            const int nc = gi * 4 + ncl;
            const int xg = nc * 8 + g;
            const int base = pbase + xg;

            uint32_t bm[2][2], by[2][2], bl[2][2];
#pragma unroll
            for (int s = 0; s < 2; ++s) {
#pragma unroll
                for (int ri = 0; ri < 2; ++ri) {
                    int a = base + ofs[s][ri];
                    bm[s][ri] = m2 [a];
                    by[s][ri] = yh2[a];
                    bl[s][ri] = yl2[a];
                }
            }

            float accA[2][4] = {{0.f, 0.f, 0.f, 0.f}, {0.f, 0.f, 0.f, 0.f}};
            float accB[2][4] = {{0.f, 0.f, 0.f, 0.f}, {0.f, 0.f, 0.f, 0.f}};
#pragma unroll
            for (int s = 0; s < 2; ++s) {
#pragma unroll
                for (int m = 0; m < 2; ++m) {
                    mma16816(accA[m], Wh[m][s], bm[s]);
                    mma16816(accB[m], Wh[m][s], by[s]);
                    mma16816(accA[m], Wl[m][s], bm[s]);
                    mma16816(accB[m], Wl[m][s], by[s]);
                    mma16816(accB[m], Wh[m][s], bl[s]);
                }
            }

            // ref*A - B -> stage  (row = m*16 + half*8 + g, col = ncl*8 + 2*tig)
            const int xo = nc * 8 + 2 * tig;
            const float2 rv = *reinterpret_cast<const float2*>(&refp[wrow * 128 + xo]);
            const int colo = ncl * 8 + 2 * tig;
#pragma unroll
            for (int m = 0; m < 2; ++m) {
                *reinterpret_cast<float2*>(&wb[(m * 16 + g) * SP + colo]) =
                    make_float2(fmaf(rv.x, accA[m][0], -accB[m][0]),
                                fmaf(rv.y, accA[m][1], -accB[m][1]));
                *reinterpret_cast<float2*>(&wb[(m * 16 + 8 + g) * SP + colo]) =
                    make_float2(fmaf(rv.x, accA[m][2], -accB[m][2]),
                                fmaf(rv.y, accA[m][3], -accB[m][3]));
            }
        }
        __syncwarp();

        // coalesced drain: 8x (LDS.128 + STG.128 covering 4 full 128B lines)
#pragma unroll
        for (int it = 0; it < 8; ++it) {
            const int r = it * 4 + rr;     // ch row 0..31
            float4 v = *reinterpret_cast<const float4*>(&wb[r * SP + pxl]);
            *reinterpret_cast<float4*>(obase + (size_t)r * IMG_HW + gi * 32 + pxl) = v;
        }
        __syncwarp();
    }
}

extern "C" void kernel_launch(void* const* d_in, const int* in_sizes, int n_in,
                              void* d_out, int out_size) {
    const float* x = (const float*)d_in[0];
    const float* w = (const float*)d_in[1];
    if (n_in >= 2 && in_sizes[0] == OCH * KK) {   // defensive input-order check
        x = (const float*)d_in[1];
        w = (const float*)d_in[0];
    }
    prep_wfrag<<<16, 128>>>(w);
    dim3 grid(IMG_W / TKX, IMG_H / TKY, 8);   // 5 x 240 x 8 = 9600 CTAs
    normdepthconv_plane_kernel<<<grid, THREADS>>>(x, (float*)d_out);
}